// round 10
// baseline (speedup 1.0000x reference)
#include <cuda_runtime.h>
#include <cuda_bf16.h>
#include <cfloat>
#include <cstdint>

#define N_Q    2048
#define M_B    100000
#define M_PAD  100224
#define KNN    5
#define SPLITS 37
#define RPS    2703            /* 37*2703 = 100011 >= 100000 */
#define BT     128
#define NT     22              /* ceil(2703/128) */
#define QTILES 16
#define NCAND  (SPLITS * KNN)  /* 185 */

// ---------------------------------------------------------------------------
// device scratch (bf16 hi only: 256 B per row)
// ---------------------------------------------------------------------------
__device__ __align__(256) __nv_bfloat16 g_bank1[(size_t)M_PAD * 128];
__device__ __align__(256) __nv_bfloat16 g_feat1[(size_t)N_Q * 128];
__device__ float g_y2p[M_PAD];
__device__ __align__(256) float g_y2t[(size_t)SPLITS * NT * 128];  // tile-aligned, INF-padded
__device__ float g_scratch[(size_t)N_Q * NCAND];

#define SWZ(o) ((o) ^ (((o) >> 3) & 0x70))

__device__ __forceinline__ uint32_t smem_u32(const void* p) {
    uint32_t a;
    asm("{ .reg .u64 t; cvta.to.shared.u64 t, %1; cvt.u32.u64 %0, t; }" : "=r"(a) : "l"(p));
    return a;
}

#define CP16(dst, src) asm volatile("cp.async.cg.shared.global [%0], [%1], 16;" :: "r"(dst), "l"(src))
#define CP_COMMIT()    asm volatile("cp.async.commit_group;" ::: "memory")
#define CP_WAIT1()     asm volatile("cp.async.wait_group 1;" ::: "memory")
#define CP_WAIT0()     asm volatile("cp.async.wait_group 0;" ::: "memory")

#define LDSM4(r0, r1, r2, r3, a)                                               \
    asm volatile("ldmatrix.sync.aligned.m8n8.x4.shared.b16 {%0,%1,%2,%3}, [%4];" \
        : "=r"(r0), "=r"(r1), "=r"(r2), "=r"(r3) : "r"(a))

__device__ __forceinline__ void mma16816(float* c,
    uint32_t a0, uint32_t a1, uint32_t a2, uint32_t a3, uint32_t b0, uint32_t b1) {
    asm("mma.sync.aligned.m16n8k16.row.col.f32.bf16.bf16.f32 "
        "{%0,%1,%2,%3}, {%4,%5,%6,%7}, {%8,%9}, {%0,%1,%2,%3};"
        : "+f"(c[0]), "+f"(c[1]), "+f"(c[2]), "+f"(c[3])
        : "r"(a0), "r"(a1), "r"(a2), "r"(a3), "r"(b0), "r"(b1));
}

__device__ __forceinline__ void insert5(float* t, float d) {
    t[4] = d;
#pragma unroll
    for (int s = 4; s > 0; --s) {
        float lo = fminf(t[s], t[s - 1]);
        float hi = fmaxf(t[s], t[s - 1]);
        t[s - 1] = lo; t[s] = hi;
    }
}

// ---------------------------------------------------------------------------
// prep: fp32 -> bf16 hi; bank also y2 (+INF padding); y2 tiled gather
// ---------------------------------------------------------------------------
__global__ void prep_bank(const float* __restrict__ bank) {
    int r = (blockIdx.x * blockDim.x + threadIdx.x) >> 5;
    int lane = threadIdx.x & 31;
    if (r >= M_PAD) return;
    float4 v = make_float4(0.f, 0.f, 0.f, 0.f);
    if (r < M_B) v = *reinterpret_cast<const float4*>(bank + (size_t)r * 128 + lane * 4);
    __nv_bfloat16 h[4] = {__float2bfloat16(v.x), __float2bfloat16(v.y),
                          __float2bfloat16(v.z), __float2bfloat16(v.w)};
    *reinterpret_cast<uint2*>(&g_bank1[(size_t)r * 128 + lane * 4]) = *reinterpret_cast<const uint2*>(h);
    float s = v.x * v.x + v.y * v.y + v.z * v.z + v.w * v.w;
#pragma unroll
    for (int o = 16; o; o >>= 1) s += __shfl_xor_sync(0xFFFFFFFFu, s, o);
    if (lane == 0) g_y2p[r] = (r < M_B) ? s : __int_as_float(0x7f800000);
}

__global__ void prep_feat(const float* __restrict__ feat) {
    int r = (blockIdx.x * blockDim.x + threadIdx.x) >> 5;
    int lane = threadIdx.x & 31;
    if (r >= N_Q) return;
    float4 v = *reinterpret_cast<const float4*>(feat + (size_t)r * 128 + lane * 4);
    __nv_bfloat16 h[4] = {__float2bfloat16(v.x), __float2bfloat16(v.y),
                          __float2bfloat16(v.z), __float2bfloat16(v.w)};
    *reinterpret_cast<uint2*>(&g_feat1[(size_t)r * 128 + lane * 4]) = *reinterpret_cast<const uint2*>(h);
}

// tile-aligned y2 with INF padding beyond each split's valid range
__global__ void prep_y2t() {
    int idx = blockIdx.x * blockDim.x + threadIdx.x;
    if (idx >= SPLITS * NT * 128) return;
    int s = idx / (NT * 128);
    int local = idx - s * (NT * 128);
    float v = __int_as_float(0x7f800000);
    if (local < RPS) v = g_y2p[s * RPS + local];   // already INF for rows >= M_B
    g_y2t[idx] = v;
}

// ---------------------------------------------------------------------------
// main: 128q x 128m x K128 bf16 HMMA + screened fused top-5, occ 2
// smem: A 32KB @0 (2 chunks x 16KB) | B 2x32KB @32768 | y2 2x512B @98304
// ---------------------------------------------------------------------------
#define SMEM_SZ 99328

__global__ void __launch_bounds__(256, 2)
knn_main() {
    extern __shared__ __align__(1024) char smem[];
    const uint32_t sb = smem_u32(smem);
    const int tid  = threadIdx.x;
    const int wid  = tid >> 5;
    const int lane = tid & 31;
    const int wq = (wid >> 1) * 32;     // 0,32,64,96
    const int wm = (wid & 1) * 64;      // 0,64

    const int split  = blockIdx.x;
    const int q0     = blockIdx.y * 128;
    const int rbegin = split * RPS;

    // ---- A tile: 128 rows x 256B, swizzled, loaded once ----
    {
        const char* ga = (const char*)g_feat1 + (size_t)q0 * 256;
#pragma unroll
        for (int it = 0; it < 8; ++it) {
            int seg = it * 256 + tid;
            int row = seg >> 4, by = (seg & 15) << 4;
            int ch = by >> 7, inb = by & 127;
            float4 v = *reinterpret_cast<const float4*>(ga + row * 256 + by);
            *reinterpret_cast<float4*>(smem + ch * 16384 + SWZ(row * 128 + inb)) = v;
        }
    }

    // ---- lane-invariant fragment addresses ----
    const int ka = (lane & 16) ? 16 : 0;
    uint32_t aBase[2]; int xa[2];
#pragma unroll
    for (int mt = 0; mt < 2; ++mt) {
        int mrow = wq + mt * 16 + (lane & 15);
        aBase[mt] = sb + mrow * 128;
        xa[mt] = (mrow & 7) * 16;
    }
    const int kb = ((lane >> 4) & 1) * 16;
    const int nr = ((lane >> 3) & 1) * 8 + (lane & 7);
    uint32_t bRel[4]; int xb[4];
#pragma unroll
    for (int g = 0; g < 4; ++g) {
        int nrow = wm + g * 16 + nr;
        bRel[g] = nrow * 128;
        xb[g] = (nrow & 7) * 16;
    }

    // ---- B + y2 stage, fully async (y2 from tile-aligned g_y2t) ----
    auto stageB = [&](int st, int t) {
        const char* gb = (const char*)g_bank1 + (size_t)(rbegin + t * BT) * 256;
        uint32_t bs = sb + 32768 + st * 32768;
#pragma unroll
        for (int it = 0; it < 8; ++it) {
            int seg = it * 256 + tid;
            int row = seg >> 4, by = (seg & 15) << 4;
            int ch = by >> 7, inb = by & 127;
            CP16(bs + ch * 16384 + SWZ(row * 128 + inb), gb + row * 256 + by);
        }
        if (tid < 32)
            CP16(sb + 98304 + st * 512 + tid * 16,
                 (const char*)g_y2t + ((size_t)(split * NT + t) * 512) + tid * 16);
        CP_COMMIT();
    };

    stageB(0, 0);

    float top[4][KNN];
#pragma unroll
    for (int i = 0; i < 4; ++i)
#pragma unroll
        for (int s = 0; s < KNN; ++s) top[i][s] = FLT_MAX;

    for (int t = 0; t < NT; ++t) {
        const int st = t & 1;
        if (t + 1 < NT) { stageB(st ^ 1, t + 1); CP_WAIT1(); }
        else            { CP_WAIT0(); }
        __syncthreads();

        float acc[2][8][4];
#pragma unroll
        for (int mt = 0; mt < 2; ++mt)
#pragma unroll
            for (int nt = 0; nt < 8; ++nt)
#pragma unroll
                for (int c = 0; c < 4; ++c) acc[mt][nt][c] = 0.f;

        const uint32_t bs = sb + 32768 + st * 32768;
#pragma unroll
        for (int ks = 0; ks < 8; ++ks) {
            const uint32_t ca = (ks >> 2) * 16384u;
            const int kk = (ks & 3) * 32;
            uint32_t A[2][4], B[4][4];
            LDSM4(A[0][0], A[0][1], A[0][2], A[0][3], aBase[0] + ca + ((kk + ka) ^ xa[0]));
            LDSM4(A[1][0], A[1][1], A[1][2], A[1][3], aBase[1] + ca + ((kk + ka) ^ xa[1]));
#pragma unroll
            for (int g = 0; g < 4; ++g)
                LDSM4(B[g][0], B[g][1], B[g][2], B[g][3],
                      bs + ca + bRel[g] + ((kk + kb) ^ xb[g]));
#pragma unroll
            for (int mt = 0; mt < 2; ++mt)
#pragma unroll
                for (int nt = 0; nt < 8; ++nt)
                    mma16816(acc[mt][nt], A[mt][0], A[mt][1], A[mt][2], A[mt][3],
                             B[nt >> 1][nt & 1], B[nt >> 1][(nt & 1) + 2]);
        }

        // ---- screened epilogue: distances overwrite acc, min-tree per list,
        //      full scan only when the group min beats the current 5th-best ----
        {
            const float* y2s = (const float*)(smem + 98304 + st * 512);
            float2 yv[8];
#pragma unroll
            for (int nt = 0; nt < 8; ++nt)
                yv[nt] = *reinterpret_cast<const float2*>(y2s + wm + nt * 8 + (lane & 3) * 2);

#pragma unroll
            for (int mt = 0; mt < 2; ++mt) {
#pragma unroll
                for (int half = 0; half < 2; ++half) {
                    const int ti = mt * 2 + half;
                    float gmin = __int_as_float(0x7f800000);
#pragma unroll
                    for (int nt = 0; nt < 8; ++nt) {
                        float d0 = fmaf(-2.0f, acc[mt][nt][half * 2 + 0], yv[nt].x);
                        float d1 = fmaf(-2.0f, acc[mt][nt][half * 2 + 1], yv[nt].y);
                        acc[mt][nt][half * 2 + 0] = d0;
                        acc[mt][nt][half * 2 + 1] = d1;
                        gmin = fminf(gmin, fminf(d0, d1));
                    }
                    if (gmin < top[ti][KNN - 1]) {
#pragma unroll
                        for (int nt = 0; nt < 8; ++nt) {
#pragma unroll
                            for (int j = 0; j < 2; ++j) {
                                float d = acc[mt][nt][half * 2 + j];
                                if (d < top[ti][KNN - 1]) insert5(top[ti], d);
                            }
                        }
                    }
                }
            }
        }
        __syncthreads();
    }

    // ---- merge 8 lists per query through smem (reuse B region) ----
    float* mbuf = (float*)(smem + 32768);
    const int lid = (wid & 1) * 4 + (lane & 3);
#pragma unroll
    for (int ti = 0; ti < 4; ++ti) {
        int mt = ti >> 1, half = ti & 1;
        int qloc = wq + mt * 16 + half * 8 + (lane >> 2);
        float* dst = mbuf + (qloc * 8 + lid) * KNN;
#pragma unroll
        for (int s = 0; s < KNN; ++s) dst[s] = top[ti][s];
    }
    __syncthreads();
    if (tid < 128) {
        float best[KNN] = {FLT_MAX, FLT_MAX, FLT_MAX, FLT_MAX, FLT_MAX};
        const float* src = mbuf + tid * 8 * KNN;
#pragma unroll
        for (int c = 0; c < 8 * KNN; ++c) {
            float d = src[c];
            if (d < best[KNN - 1]) insert5(best, d);
        }
        float* dst = g_scratch + ((size_t)(q0 + tid) * SPLITS + split) * KNN;
#pragma unroll
        for (int s = 0; s < KNN; ++s) dst[s] = best[s];
    }
}

// ---------------------------------------------------------------------------
// phaseB: one warp per query — 5-pass warp-min select over 185 candidates
// ---------------------------------------------------------------------------
__global__ void phaseB(const float* __restrict__ feat,
                       const float* __restrict__ minv,
                       const float* __restrict__ maxv,
                       float* __restrict__ out) {
    const int lane = threadIdx.x & 31;
    const int q = blockIdx.x * (blockDim.x >> 5) + (threadIdx.x >> 5);
    if (q >= N_Q) return;

    const float INF = __int_as_float(0x7f800000);
    const float* src = g_scratch + (size_t)q * NCAND;
    float v[6];
#pragma unroll
    for (int i = 0; i < 6; ++i) {
        int idx = i * 32 + lane;
        v[i] = (idx < NCAND) ? src[idx] : INF;
    }

    // x2 warp-reduced
    float4 fv = *reinterpret_cast<const float4*>(feat + (size_t)q * 128 + lane * 4);
    float x2 = fv.x * fv.x + fv.y * fv.y + fv.z * fv.z + fv.w * fv.w;
#pragma unroll
    for (int o = 16; o; o >>= 1) x2 += __shfl_xor_sync(0xFFFFFFFFu, x2, o);

    float best[KNN];
#pragma unroll
    for (int p = 0; p < KNN; ++p) {
        float lm = v[0];
#pragma unroll
        for (int i = 1; i < 6; ++i) lm = fminf(lm, v[i]);
        float wm = lm;
#pragma unroll
        for (int o = 16; o; o >>= 1) wm = fminf(wm, __shfl_xor_sync(0xFFFFFFFFu, wm, o));
        unsigned mask = __ballot_sync(0xFFFFFFFFu, lm == wm);
        int leader = __ffs(mask) - 1;
        if (lane == leader) {
            bool done = false;
#pragma unroll
            for (int i = 0; i < 6; ++i)
                if (!done && v[i] == wm) { v[i] = INF; done = true; }
        }
        best[p] = wm;
    }

    if (lane == 0) {
        float mn = *minv, mx = *maxv;
        float inv = 1.0f / (mx - mn);
        float acc = 0.f;
#pragma unroll
        for (int s = 0; s < KNN; ++s) {
            float d2 = fmaxf(x2 + best[s], 0.f);
            acc += (sqrtf(d2) - mn) * inv;
        }
        out[q] = acc * (1.0f / (float)KNN);
    }
}

// ---------------------------------------------------------------------------
extern "C" void kernel_launch(void* const* d_in, const int* in_sizes, int n_in,
                              void* d_out, int out_size) {
    (void)in_sizes; (void)n_in; (void)out_size;
    const float* feat = (const float*)d_in[0];
    const float* bank = (const float*)d_in[1];
    const float* minv = (const float*)d_in[2];
    const float* maxv = (const float*)d_in[3];
    float* out = (float*)d_out;

    prep_bank<<<(M_PAD + 7) / 8, 256>>>(bank);
    prep_feat<<<(N_Q + 7) / 8, 256>>>(feat);
    prep_y2t<<<(SPLITS * NT * 128 + 255) / 256, 256>>>();

    cudaFuncSetAttribute(knn_main, cudaFuncAttributeMaxDynamicSharedMemorySize, SMEM_SZ);
    knn_main<<<dim3(SPLITS, QTILES), 256, SMEM_SZ>>>();

    phaseB<<<(N_Q * 32 + 255) / 256, 256>>>(feat, minv, maxv, out);
}

// round 11
// speedup vs baseline: 1.0546x; 1.0546x over previous
#include <cuda_runtime.h>
#include <cuda_bf16.h>
#include <cfloat>
#include <cstdint>

#define N_Q    2048
#define M_B    100000
#define M_PAD  100224
#define KNN    5
#define SPLITS 37
#define RPS    2703            /* 37*2703 = 100011 >= 100000 */
#define BT     128
#define NT     22              /* ceil(2703/128) */
#define QTILES 16
#define NCAND  (SPLITS * KNN)  /* 185 */

// ---------------------------------------------------------------------------
// device scratch. g_bank1 holds bf16(-2*y): power-of-2 scale, exact.
// ---------------------------------------------------------------------------
__device__ __align__(256) __nv_bfloat16 g_bank1[(size_t)M_PAD * 128];
__device__ __align__(256) __nv_bfloat16 g_feat1[(size_t)N_Q * 128];
__device__ float g_y2p[M_PAD];
__device__ __align__(256) float g_y2t[(size_t)SPLITS * NT * 128];  // tile-aligned, INF-padded
__device__ float g_scratch[(size_t)N_Q * NCAND];

#define SWZ(o) ((o) ^ (((o) >> 3) & 0x70))

__device__ __forceinline__ uint32_t smem_u32(const void* p) {
    uint32_t a;
    asm("{ .reg .u64 t; cvta.to.shared.u64 t, %1; cvt.u32.u64 %0, t; }" : "=r"(a) : "l"(p));
    return a;
}

#define CP16(dst, src) asm volatile("cp.async.cg.shared.global [%0], [%1], 16;" :: "r"(dst), "l"(src))
#define CP_COMMIT()    asm volatile("cp.async.commit_group;" ::: "memory")
#define CP_WAIT1()     asm volatile("cp.async.wait_group 1;" ::: "memory")
#define CP_WAIT0()     asm volatile("cp.async.wait_group 0;" ::: "memory")

#define LDSM4(r0, r1, r2, r3, a)                                               \
    asm volatile("ldmatrix.sync.aligned.m8n8.x4.shared.b16 {%0,%1,%2,%3}, [%4];" \
        : "=r"(r0), "=r"(r1), "=r"(r2), "=r"(r3) : "r"(a))

__device__ __forceinline__ void mma16816(float* c,
    uint32_t a0, uint32_t a1, uint32_t a2, uint32_t a3, uint32_t b0, uint32_t b1) {
    asm("mma.sync.aligned.m16n8k16.row.col.f32.bf16.bf16.f32 "
        "{%0,%1,%2,%3}, {%4,%5,%6,%7}, {%8,%9}, {%0,%1,%2,%3};"
        : "+f"(c[0]), "+f"(c[1]), "+f"(c[2]), "+f"(c[3])
        : "r"(a0), "r"(a1), "r"(a2), "r"(a3), "r"(b0), "r"(b1));
}

__device__ __forceinline__ void insert5(float* t, float d) {
    t[4] = d;
#pragma unroll
    for (int s = 4; s > 0; --s) {
        float lo = fminf(t[s], t[s - 1]);
        float hi = fmaxf(t[s], t[s - 1]);
        t[s - 1] = lo; t[s] = hi;
    }
}

// ---------------------------------------------------------------------------
// prep: fp32 -> bf16; bank stores -2*y (exact scale) + y2 (+INF padding)
// ---------------------------------------------------------------------------
__global__ void prep_bank(const float* __restrict__ bank) {
    int r = (blockIdx.x * blockDim.x + threadIdx.x) >> 5;
    int lane = threadIdx.x & 31;
    if (r >= M_PAD) return;
    float4 v = make_float4(0.f, 0.f, 0.f, 0.f);
    if (r < M_B) v = *reinterpret_cast<const float4*>(bank + (size_t)r * 128 + lane * 4);
    __nv_bfloat16 h[4] = {__float2bfloat16(-2.f * v.x), __float2bfloat16(-2.f * v.y),
                          __float2bfloat16(-2.f * v.z), __float2bfloat16(-2.f * v.w)};
    *reinterpret_cast<uint2*>(&g_bank1[(size_t)r * 128 + lane * 4]) = *reinterpret_cast<const uint2*>(h);
    float s = v.x * v.x + v.y * v.y + v.z * v.z + v.w * v.w;
#pragma unroll
    for (int o = 16; o; o >>= 1) s += __shfl_xor_sync(0xFFFFFFFFu, s, o);
    if (lane == 0) g_y2p[r] = (r < M_B) ? s : __int_as_float(0x7f800000);
}

__global__ void prep_feat(const float* __restrict__ feat) {
    int r = (blockIdx.x * blockDim.x + threadIdx.x) >> 5;
    int lane = threadIdx.x & 31;
    if (r >= N_Q) return;
    float4 v = *reinterpret_cast<const float4*>(feat + (size_t)r * 128 + lane * 4);
    __nv_bfloat16 h[4] = {__float2bfloat16(v.x), __float2bfloat16(v.y),
                          __float2bfloat16(v.z), __float2bfloat16(v.w)};
    *reinterpret_cast<uint2*>(&g_feat1[(size_t)r * 128 + lane * 4]) = *reinterpret_cast<const uint2*>(h);
}

// tile-aligned y2 with INF padding beyond each split's valid range
__global__ void prep_y2t() {
    int idx = blockIdx.x * blockDim.x + threadIdx.x;
    if (idx >= SPLITS * NT * 128) return;
    int s = idx / (NT * 128);
    int local = idx - s * (NT * 128);
    float v = __int_as_float(0x7f800000);
    if (local < RPS) v = g_y2p[s * RPS + local];   // already INF for rows >= M_B
    g_y2t[idx] = v;
}

// ---------------------------------------------------------------------------
// main: 128q x 128m x K128 bf16 HMMA; acc initialized to y2, B pre-scaled by
// -2 => acc ends as the distance d' directly. Screened top-5, occ 2.
// smem: A 32KB @0 (2 chunks x 16KB) | B 2x32KB @32768 | y2 2x512B @98304
// ---------------------------------------------------------------------------
#define SMEM_SZ 99328

__global__ void __launch_bounds__(256, 2)
knn_main() {
    extern __shared__ __align__(1024) char smem[];
    const uint32_t sb = smem_u32(smem);
    const int tid  = threadIdx.x;
    const int wid  = tid >> 5;
    const int lane = tid & 31;
    const int wq = (wid >> 1) * 32;     // 0,32,64,96
    const int wm = (wid & 1) * 64;      // 0,64

    const int split  = blockIdx.x;
    const int q0     = blockIdx.y * 128;
    const int rbegin = split * RPS;

    // ---- A tile: 128 rows x 256B, swizzled, loaded once ----
    {
        const char* ga = (const char*)g_feat1 + (size_t)q0 * 256;
#pragma unroll
        for (int it = 0; it < 8; ++it) {
            int seg = it * 256 + tid;
            int row = seg >> 4, by = (seg & 15) << 4;
            int ch = by >> 7, inb = by & 127;
            float4 v = *reinterpret_cast<const float4*>(ga + row * 256 + by);
            *reinterpret_cast<float4*>(smem + ch * 16384 + SWZ(row * 128 + inb)) = v;
        }
    }

    // ---- lane-invariant fragment addresses ----
    const int ka = (lane & 16) ? 16 : 0;
    uint32_t aBase[2]; int xa[2];
#pragma unroll
    for (int mt = 0; mt < 2; ++mt) {
        int mrow = wq + mt * 16 + (lane & 15);
        aBase[mt] = sb + mrow * 128;
        xa[mt] = (mrow & 7) * 16;
    }
    const int kb = ((lane >> 4) & 1) * 16;
    const int nr = ((lane >> 3) & 1) * 8 + (lane & 7);
    uint32_t bRel[4]; int xb[4];
#pragma unroll
    for (int g = 0; g < 4; ++g) {
        int nrow = wm + g * 16 + nr;
        bRel[g] = nrow * 128;
        xb[g] = (nrow & 7) * 16;
    }

    // ---- stageB: strength-reduced (swizzle additive in it*2048) ----
    const int srcOff = (tid >> 4) * 256 + (tid & 15) * 16;
    const uint32_t dstOff =
        ((uint32_t)((tid & 15) << 4) >> 7) * 16384u +
        SWZ((uint32_t)((tid >> 4) * 128 + (((tid & 15) << 4) & 127)));

    auto stageB = [&](int st, int t) {
        const char* gb = (const char*)g_bank1 + (size_t)(rbegin + t * BT) * 256 + srcOff;
        uint32_t bs = sb + 32768 + st * 32768 + dstOff;
#pragma unroll
        for (int it = 0; it < 8; ++it)
            CP16(bs + it * 2048, gb + it * 4096);
        if (tid < 32)
            CP16(sb + 98304 + st * 512 + tid * 16,
                 (const char*)g_y2t + ((size_t)(split * NT + t) * 512) + tid * 16);
        CP_COMMIT();
    };

    stageB(0, 0);

    float top[4][KNN];
#pragma unroll
    for (int i = 0; i < 4; ++i)
#pragma unroll
        for (int s = 0; s < KNN; ++s) top[i][s] = FLT_MAX;

    for (int t = 0; t < NT; ++t) {
        const int st = t & 1;
        if (t + 1 < NT) { stageB(st ^ 1, t + 1); CP_WAIT1(); }
        else            { CP_WAIT0(); }
        __syncthreads();

        // ---- init accumulators with y2[col]: MMA then yields d' directly ----
        float acc[2][8][4];
        {
            const float* y2s = (const float*)(smem + 98304 + st * 512);
#pragma unroll
            for (int nt = 0; nt < 8; ++nt) {
                float2 yv = *reinterpret_cast<const float2*>(y2s + wm + nt * 8 + (lane & 3) * 2);
                acc[0][nt][0] = yv.x; acc[0][nt][1] = yv.y;
                acc[0][nt][2] = yv.x; acc[0][nt][3] = yv.y;
                acc[1][nt][0] = yv.x; acc[1][nt][1] = yv.y;
                acc[1][nt][2] = yv.x; acc[1][nt][3] = yv.y;
            }
        }

        const uint32_t bs = sb + 32768 + st * 32768;
#pragma unroll
        for (int ks = 0; ks < 8; ++ks) {
            const uint32_t ca = (ks >> 2) * 16384u;
            const int kk = (ks & 3) * 32;
            uint32_t A[2][4], B[4][4];
            LDSM4(A[0][0], A[0][1], A[0][2], A[0][3], aBase[0] + ca + ((kk + ka) ^ xa[0]));
            LDSM4(A[1][0], A[1][1], A[1][2], A[1][3], aBase[1] + ca + ((kk + ka) ^ xa[1]));
#pragma unroll
            for (int g = 0; g < 4; ++g)
                LDSM4(B[g][0], B[g][1], B[g][2], B[g][3],
                      bs + ca + bRel[g] + ((kk + kb) ^ xb[g]));
#pragma unroll
            for (int mt = 0; mt < 2; ++mt)
#pragma unroll
                for (int nt = 0; nt < 8; ++nt)
                    mma16816(acc[mt][nt], A[mt][0], A[mt][1], A[mt][2], A[mt][3],
                             B[nt >> 1][nt & 1], B[nt >> 1][(nt & 1) + 2]);
        }

        // ---- screened top-5: acc IS the distance; min-tree + rare scan ----
#pragma unroll
        for (int mt = 0; mt < 2; ++mt) {
#pragma unroll
            for (int half = 0; half < 2; ++half) {
                const int ti = mt * 2 + half;
                float gmin = __int_as_float(0x7f800000);
#pragma unroll
                for (int nt = 0; nt < 8; ++nt)
                    gmin = fminf(gmin,
                                 fminf(acc[mt][nt][half * 2 + 0], acc[mt][nt][half * 2 + 1]));
                if (gmin < top[ti][KNN - 1]) {
#pragma unroll
                    for (int nt = 0; nt < 8; ++nt) {
#pragma unroll
                        for (int j = 0; j < 2; ++j) {
                            float d = acc[mt][nt][half * 2 + j];
                            if (d < top[ti][KNN - 1]) insert5(top[ti], d);
                        }
                    }
                }
            }
        }
        __syncthreads();
    }

    // ---- merge 8 lists per query through smem (reuse B region) ----
    float* mbuf = (float*)(smem + 32768);
    const int lid = (wid & 1) * 4 + (lane & 3);
#pragma unroll
    for (int ti = 0; ti < 4; ++ti) {
        int mt = ti >> 1, half = ti & 1;
        int qloc = wq + mt * 16 + half * 8 + (lane >> 2);
        float* dst = mbuf + (qloc * 8 + lid) * KNN;
#pragma unroll
        for (int s = 0; s < KNN; ++s) dst[s] = top[ti][s];
    }
    __syncthreads();
    if (tid < 128) {
        float best[KNN] = {FLT_MAX, FLT_MAX, FLT_MAX, FLT_MAX, FLT_MAX};
        const float* src = mbuf + tid * 8 * KNN;
#pragma unroll
        for (int c = 0; c < 8 * KNN; ++c) {
            float d = src[c];
            if (d < best[KNN - 1]) insert5(best, d);
        }
        float* dst = g_scratch + ((size_t)(q0 + tid) * SPLITS + split) * KNN;
#pragma unroll
        for (int s = 0; s < KNN; ++s) dst[s] = best[s];
    }
}

// ---------------------------------------------------------------------------
// phaseB: one warp per query — 5-pass warp-min select over 185 candidates
// ---------------------------------------------------------------------------
__global__ void phaseB(const float* __restrict__ feat,
                       const float* __restrict__ minv,
                       const float* __restrict__ maxv,
                       float* __restrict__ out) {
    const int lane = threadIdx.x & 31;
    const int q = blockIdx.x * (blockDim.x >> 5) + (threadIdx.x >> 5);
    if (q >= N_Q) return;

    const float INF = __int_as_float(0x7f800000);
    const float* src = g_scratch + (size_t)q * NCAND;
    float v[6];
#pragma unroll
    for (int i = 0; i < 6; ++i) {
        int idx = i * 32 + lane;
        v[i] = (idx < NCAND) ? src[idx] : INF;
    }

    // x2 warp-reduced
    float4 fv = *reinterpret_cast<const float4*>(feat + (size_t)q * 128 + lane * 4);
    float x2 = fv.x * fv.x + fv.y * fv.y + fv.z * fv.z + fv.w * fv.w;
#pragma unroll
    for (int o = 16; o; o >>= 1) x2 += __shfl_xor_sync(0xFFFFFFFFu, x2, o);

    float best[KNN];
#pragma unroll
    for (int p = 0; p < KNN; ++p) {
        float lm = v[0];
#pragma unroll
        for (int i = 1; i < 6; ++i) lm = fminf(lm, v[i]);
        float wm = lm;
#pragma unroll
        for (int o = 16; o; o >>= 1) wm = fminf(wm, __shfl_xor_sync(0xFFFFFFFFu, wm, o));
        unsigned mask = __ballot_sync(0xFFFFFFFFu, lm == wm);
        int leader = __ffs(mask) - 1;
        if (lane == leader) {
            bool done = false;
#pragma unroll
            for (int i = 0; i < 6; ++i)
                if (!done && v[i] == wm) { v[i] = INF; done = true; }
        }
        best[p] = wm;
    }

    if (lane == 0) {
        float mn = *minv, mx = *maxv;
        float inv = 1.0f / (mx - mn);
        float acc = 0.f;
#pragma unroll
        for (int s = 0; s < KNN; ++s) {
            float d2 = fmaxf(x2 + best[s], 0.f);
            acc += (sqrtf(d2) - mn) * inv;
        }
        out[q] = acc * (1.0f / (float)KNN);
    }
}

// ---------------------------------------------------------------------------
extern "C" void kernel_launch(void* const* d_in, const int* in_sizes, int n_in,
                              void* d_out, int out_size) {
    (void)in_sizes; (void)n_in; (void)out_size;
    const float* feat = (const float*)d_in[0];
    const float* bank = (const float*)d_in[1];
    const float* minv = (const float*)d_in[2];
    const float* maxv = (const float*)d_in[3];
    float* out = (float*)d_out;

    prep_bank<<<(M_PAD + 7) / 8, 256>>>(bank);
    prep_feat<<<(N_Q + 7) / 8, 256>>>(feat);
    prep_y2t<<<(SPLITS * NT * 128 + 255) / 256, 256>>>();

    cudaFuncSetAttribute(knn_main, cudaFuncAttributeMaxDynamicSharedMemorySize, SMEM_SZ);
    knn_main<<<dim3(SPLITS, QTILES), 256, SMEM_SZ>>>();

    phaseB<<<(N_Q * 32 + 255) / 256, 256>>>(feat, minv, maxv, out);
}